// round 7
// baseline (speedup 1.0000x reference)
#include <cuda_runtime.h>
#include <cuda_bf16.h>

// SpatialMaxpool2d: x (32, 69, 128, 128) fp32, k=2, stride=2.
// Out (32, 69, 64, 64):
//   ch 0..63  : 2x2 maxpool of x[:, 0:64]
//   ch 64..65 : weighted window mean of x[:, 64:66]
//   ch 66..67 : weighted var  (x[:,66:68]·q + sum q*(u-mean)^2)
//   ch 68     : weighted cov  (x[:,68]·q + sum q^2*(u0-m0)*(u1-m1))
// Window weight q_p = A_p / sum_p A_p, A_p = sum_c |x[b,c,p]| over ALL 69 channels.
//
// R4: 2 output pixels per thread via float4 loads. Each warp now reads a full
// 512B input row per request, and its row-pair forms 1KB contiguous per
// channel -> better HBM row-buffer locality (theory: R3's 27% DRAM idle is
// page-activate overhead from scattered 256B fragments). Plain loads/stores
// (R2 proved .cs hints cost 1.5x).

#define C_TOTAL 69
#define CS      64
#define H_IN    128
#define W_IN    128
#define H_OUT   64
#define W_OUT   64
#define HW_IN   (H_IN * W_IN)      // 16384
#define HW_OUT  (H_OUT * W_OUT)    // 4096

__global__ void __launch_bounds__(128)
spatial_maxpool_kernel(const float* __restrict__ x, float* __restrict__ out, int total)
{
    int idx = blockIdx.x * blockDim.x + threadIdx.x;
    if (idx >= total) return;

    // each thread: 2 adjacent output pixels (out cols 2*j2, 2*j2+1)
    int j2 = idx & 31;              // 0..31 (pair index within row)
    int i  = (idx >> 5) & 63;       // output row
    int b  = idx >> 11;             // batch

    const float* xb   = x + (size_t)b * C_TOTAL * HW_IN;
    const float* row0 = xb + (2 * i) * W_IN + 4 * j2;   // 16B-aligned
    const float* row1 = row0 + W_IN;
    float* ob = out + (size_t)b * C_TOTAL * HW_OUT + i * W_OUT + 2 * j2;  // 8B-aligned

    // abs accumulators: pixel0 {a0..a3}, pixel1 {a4..a7}  (order: r0.x r0.y r1.x r1.y)
    float a0 = 0.f, a1 = 0.f, a2 = 0.f, a3 = 0.f;
    float a4 = 0.f, a5 = 0.f, a6 = 0.f, a7 = 0.f;

    // ---- pooled channels 0..63 ----
    #pragma unroll 4
    for (int c = 0; c < CS; ++c) {
        float4 r0 = __ldg((const float4*)(row0 + c * HW_IN));
        float4 r1 = __ldg((const float4*)(row1 + c * HW_IN));
        a0 += fabsf(r0.x); a1 += fabsf(r0.y); a2 += fabsf(r1.x); a3 += fabsf(r1.y);
        a4 += fabsf(r0.z); a5 += fabsf(r0.w); a6 += fabsf(r1.z); a7 += fabsf(r1.w);
        float2 mx;
        mx.x = fmaxf(fmaxf(r0.x, r0.y), fmaxf(r1.x, r1.y));
        mx.y = fmaxf(fmaxf(r0.z, r0.w), fmaxf(r1.z, r1.w));
        *(float2*)(ob + c * HW_OUT) = mx;
    }

    // ---- stat channels 64..68 ----
    float v[5][8];   // [chan][pix0: 0..3 | pix1: 4..7]
    #pragma unroll
    for (int t = 0; t < 5; ++t) {
        int c = CS + t;
        float4 r0 = __ldg((const float4*)(row0 + c * HW_IN));
        float4 r1 = __ldg((const float4*)(row1 + c * HW_IN));
        v[t][0] = r0.x; v[t][1] = r0.y; v[t][2] = r1.x; v[t][3] = r1.y;
        v[t][4] = r0.z; v[t][5] = r0.w; v[t][6] = r1.z; v[t][7] = r1.w;
        a0 += fabsf(r0.x); a1 += fabsf(r0.y); a2 += fabsf(r1.x); a3 += fabsf(r1.y);
        a4 += fabsf(r0.z); a5 += fabsf(r0.w); a6 += fabsf(r1.z); a7 += fabsf(r1.w);
    }

    float res[5][2];
    #pragma unroll
    for (int p = 0; p < 2; ++p) {
        float b0 = p ? a4 : a0, b1 = p ? a5 : a1, b2 = p ? a6 : a2, b3 = p ? a7 : a3;
        float inv = 1.0f / (b0 + b1 + b2 + b3);
        float q0 = b0 * inv, q1 = b1 * inv, q2 = b2 * inv, q3 = b3 * inv;
        int o = p * 4;

        float m0 = v[0][o+0]*q0 + v[0][o+1]*q1 + v[0][o+2]*q2 + v[0][o+3]*q3;
        float m1 = v[1][o+0]*q0 + v[1][o+1]*q1 + v[1][o+2]*q2 + v[1][o+3]*q3;

        float d00 = v[0][o+0]-m0, d01 = v[0][o+1]-m0, d02 = v[0][o+2]-m0, d03 = v[0][o+3]-m0;
        float d10 = v[1][o+0]-m1, d11 = v[1][o+1]-m1, d12 = v[1][o+2]-m1, d13 = v[1][o+3]-m1;

        float var0 = v[2][o+0]*q0 + v[2][o+1]*q1 + v[2][o+2]*q2 + v[2][o+3]*q3
                   + d00*d00*q0 + d01*d01*q1 + d02*d02*q2 + d03*d03*q3;
        float var1 = v[3][o+0]*q0 + v[3][o+1]*q1 + v[3][o+2]*q2 + v[3][o+3]*q3
                   + d10*d10*q0 + d11*d11*q1 + d12*d12*q2 + d13*d13*q3;

        float cov = v[4][o+0]*q0 + v[4][o+1]*q1 + v[4][o+2]*q2 + v[4][o+3]*q3
                  + d00*d10*q0*q0 + d01*d11*q1*q1 + d02*d12*q2*q2 + d03*d13*q3*q3;

        res[0][p] = m0; res[1][p] = m1; res[2][p] = var0; res[3][p] = var1; res[4][p] = cov;
    }

    #pragma unroll
    for (int t = 0; t < 5; ++t) {
        float2 w; w.x = res[t][0]; w.y = res[t][1];
        *(float2*)(ob + (CS + t) * HW_OUT) = w;
    }
}

extern "C" void kernel_launch(void* const* d_in, const int* in_sizes, int n_in,
                              void* d_out, int out_size)
{
    const float* x = (const float*)d_in[0];
    float* out = (float*)d_out;
    int total = 32 * H_OUT * (W_OUT / 2);   // 65536 threads, 2 pixels each
    int threads = 128;
    int blocks = (total + threads - 1) / threads;  // 512 blocks
    spatial_maxpool_kernel<<<blocks, threads>>>(x, out, total);
}

// round 10
// speedup vs baseline: 1.0533x; 1.0533x over previous
#include <cuda_runtime.h>
#include <cuda_bf16.h>

// SpatialMaxpool2d: x (32, 69, 128, 128) fp32, k=2, stride=2.
// Out (32, 69, 64, 64):
//   ch 0..63  : 2x2 maxpool of x[:, 0:64]
//   ch 64..65 : weighted window mean of x[:, 64:66]
//   ch 66..67 : weighted var  (x[:,66:68]·q + sum q*(u-mean)^2)
//   ch 68     : weighted cov  (x[:,68]·q + sum q^2*(u0-m0)*(u1-m1))
// Window weight q_p = A_p / sum_p A_p, A_p = sum_c |x[b,c,p]| over ALL 69 channels.
//
// R8: R1 geometry (1 px/thread, float2, 256 thr, 512 blocks, plain ld/st) but
// the 64 pooled channels are processed in chunks of 16: all 32 loads issued
// up-front, then compute + a burst of 16 stores. Phase-separates the read and
// write streams at the memory controller (fewer HBM bus turnarounds) and
// doubles reads-in-flight per warp. R2 lesson: no cache hints.

#define C_TOTAL 69
#define CS      64
#define H_IN    128
#define W_IN    128
#define H_OUT   64
#define W_OUT   64
#define HW_IN   (H_IN * W_IN)      // 16384
#define HW_OUT  (H_OUT * W_OUT)    // 4096
#define CHUNK   16

__global__ void __launch_bounds__(256)
spatial_maxpool_kernel(const float* __restrict__ x, float* __restrict__ out, int total)
{
    int idx = blockIdx.x * blockDim.x + threadIdx.x;
    if (idx >= total) return;

    int j = idx & (W_OUT - 1);
    int i = (idx >> 6) & (H_OUT - 1);
    int b = idx >> 12;

    const float* xb   = x + (size_t)b * C_TOTAL * HW_IN;
    const float* row0 = xb + (2 * i) * W_IN + 2 * j;       // top row of 2x2 window
    const float* row1 = row0 + W_IN;                        // bottom row
    float* ob = out + (size_t)b * C_TOTAL * HW_OUT + i * W_OUT + j;

    // |.| accumulators for the 4 window pixels: (0,0) (0,1) (1,0) (1,1)
    float a0 = 0.f, a1 = 0.f, a2 = 0.f, a3 = 0.f;

    // ---- pooled channels 0..63, chunked: 32 loads up-front, then 16 stores ----
    for (int cb = 0; cb < CS; cb += CHUNK) {
        float2 r0[CHUNK], r1[CHUNK];
        #pragma unroll
        for (int t = 0; t < CHUNK; ++t) {
            r0[t] = __ldg((const float2*)(row0 + (cb + t) * HW_IN));
            r1[t] = __ldg((const float2*)(row1 + (cb + t) * HW_IN));
        }
        #pragma unroll
        for (int t = 0; t < CHUNK; ++t) {
            a0 += fabsf(r0[t].x); a1 += fabsf(r0[t].y);
            a2 += fabsf(r1[t].x); a3 += fabsf(r1[t].y);
            ob[(cb + t) * HW_OUT] =
                fmaxf(fmaxf(r0[t].x, r0[t].y), fmaxf(r1[t].x, r1[t].y));
        }
    }

    // ---- stat channels 64..68: keep window values in registers ----
    float v[5][4];
    #pragma unroll
    for (int t = 0; t < 5; ++t) {
        int c = CS + t;
        float2 r0 = __ldg((const float2*)(row0 + c * HW_IN));
        float2 r1 = __ldg((const float2*)(row1 + c * HW_IN));
        v[t][0] = r0.x; v[t][1] = r0.y; v[t][2] = r1.x; v[t][3] = r1.y;
        a0 += fabsf(r0.x); a1 += fabsf(r0.y);
        a2 += fabsf(r1.x); a3 += fabsf(r1.y);
    }

    // normalized window weights (scale by 1/sqrt(cs) cancels)
    float s = a0 + a1 + a2 + a3;
    float inv = 1.0f / s;
    float q0 = a0 * inv, q1 = a1 * inv, q2 = a2 * inv, q3 = a3 * inv;

    // means of u-channels (64, 65)
    float m0 = v[0][0] * q0 + v[0][1] * q1 + v[0][2] * q2 + v[0][3] * q3;
    float m1 = v[1][0] * q0 + v[1][1] * q1 + v[1][2] * q2 + v[1][3] * q3;

    // var = x[66+c]·q + sum q*(u - m)^2
    float d00 = v[0][0] - m0, d01 = v[0][1] - m0, d02 = v[0][2] - m0, d03 = v[0][3] - m0;
    float d10 = v[1][0] - m1, d11 = v[1][1] - m1, d12 = v[1][2] - m1, d13 = v[1][3] - m1;

    float var0 = v[2][0] * q0 + v[2][1] * q1 + v[2][2] * q2 + v[2][3] * q3
               + d00 * d00 * q0 + d01 * d01 * q1 + d02 * d02 * q2 + d03 * d03 * q3;
    float var1 = v[3][0] * q0 + v[3][1] * q1 + v[3][2] * q2 + v[3][3] * q3
               + d10 * d10 * q0 + d11 * d11 * q1 + d12 * d12 * q2 + d13 * d13 * q3;

    // cov = x[68]·q + sum q^2*(u0-m0)*(u1-m1)
    float cov = v[4][0] * q0 + v[4][1] * q1 + v[4][2] * q2 + v[4][3] * q3
              + d00 * d10 * q0 * q0 + d01 * d11 * q1 * q1
              + d02 * d12 * q2 * q2 + d03 * d13 * q3 * q3;

    ob[(CS + 0) * HW_OUT] = m0;
    ob[(CS + 1) * HW_OUT] = m1;
    ob[(CS + 2) * HW_OUT] = var0;
    ob[(CS + 3) * HW_OUT] = var1;
    ob[(CS + 4) * HW_OUT] = cov;
}

extern "C" void kernel_launch(void* const* d_in, const int* in_sizes, int n_in,
                              void* d_out, int out_size)
{
    const float* x = (const float*)d_in[0];
    float* out = (float*)d_out;
    int total = 32 * H_OUT * W_OUT;  // 131072 output pixels
    int threads = 256;
    int blocks = (total + threads - 1) / threads;  // 512 blocks
    spatial_maxpool_kernel<<<blocks, threads>>>(x, out, total);
}